// round 3
// baseline (speedup 1.0000x reference)
#include <cuda_runtime.h>
#include <cstddef>

// Problem constants (fixed by the reference)
#define B_  16
#define S_  512
#define D_  1024
#define H_  16
#define DH_ 64

// Scratch (static device globals: allocation-free per harness rules)
__device__ float g_Q[B_ * S_ * D_];
__device__ float g_K[B_ * S_ * D_];
__device__ float g_V[B_ * S_ * D_];
__device__ float g_A[B_ * S_ * D_];

// ---------------------------------------------------------------------------
// SGEMM: C[M,N] = A[M,K] @ W[K,N] + bias[N]   (all row-major, dims % tile == 0)
// 128x128 block tile, BK=16, 256 threads, 8x8 per-thread register tile.
// ---------------------------------------------------------------------------
__global__ __launch_bounds__(256) void sgemm_bias(
    const float* __restrict__ A, const float* __restrict__ W,
    const float* __restrict__ bias, float* __restrict__ C,
    int M, int N, int K)
{
    constexpr int BM = 128, BN = 128, BK = 16;
    __shared__ float As[BK][BM + 4];  // +4 pad: kills transpose-store conflicts
    __shared__ float Ws[BK][BN];

    const int tid = threadIdx.x;
    const int m0 = blockIdx.y * BM;
    const int n0 = blockIdx.x * BN;
    const int ty = tid >> 4;   // 0..15
    const int tx = tid & 15;   // 0..15

    float acc[8][8];
#pragma unroll
    for (int i = 0; i < 8; i++)
#pragma unroll
        for (int j = 0; j < 8; j++) acc[i][j] = 0.f;

    for (int k0 = 0; k0 < K; k0 += BK) {
#pragma unroll
        for (int p = 0; p < 2; p++) {
            int f = tid + p * 256;            // 512 float4 per tile
            int arow = f >> 2, ac4 = f & 3;   // A: 128 rows x 4 float4
            float4 av = *(const float4*)(A + (size_t)(m0 + arow) * K + k0 + ac4 * 4);
            As[ac4 * 4 + 0][arow] = av.x;
            As[ac4 * 4 + 1][arow] = av.y;
            As[ac4 * 4 + 2][arow] = av.z;
            As[ac4 * 4 + 3][arow] = av.w;
            int wrow = f >> 5, wc4 = f & 31;  // W: 16 rows x 32 float4
            *(float4*)(&Ws[wrow][wc4 * 4]) =
                *(const float4*)(W + (size_t)(k0 + wrow) * N + n0 + wc4 * 4);
        }
        __syncthreads();

#pragma unroll
        for (int kk = 0; kk < BK; kk++) {
            float a[8], b[8];
            *(float4*)(a)     = *(float4*)(&As[kk][ty * 8]);
            *(float4*)(a + 4) = *(float4*)(&As[kk][ty * 8 + 4]);
            *(float4*)(b)     = *(float4*)(&Ws[kk][tx * 8]);
            *(float4*)(b + 4) = *(float4*)(&Ws[kk][tx * 8 + 4]);
#pragma unroll
            for (int i = 0; i < 8; i++)
#pragma unroll
                for (int j = 0; j < 8; j++)
                    acc[i][j] = fmaf(a[i], b[j], acc[i][j]);
        }
        __syncthreads();
    }

#pragma unroll
    for (int i = 0; i < 8; i++) {
        int row = m0 + ty * 8 + i;
#pragma unroll
        for (int j4 = 0; j4 < 2; j4++) {
            int col = n0 + tx * 8 + j4 * 4;
            float4 o;
            o.x = acc[i][j4 * 4 + 0] + bias[col + 0];
            o.y = acc[i][j4 * 4 + 1] + bias[col + 1];
            o.z = acc[i][j4 * 4 + 2] + bias[col + 2];
            o.w = acc[i][j4 * 4 + 3] + bias[col + 3];
            *(float4*)(C + (size_t)row * N + col) = o;
        }
    }
}

// ---------------------------------------------------------------------------
// Flash attention, fp32. One thread = one query row. KT=16 key/value rows per
// shared tile. Online softmax; key-padding mask via lengths; early exit past
// the last valid key tile (tiles fully past `len` contribute exactly zero).
// grid: (S/128, H, B), block: 128
// ---------------------------------------------------------------------------
__global__ __launch_bounds__(128) void attn_kernel(
    const float* __restrict__ Q, const float* __restrict__ K,
    const float* __restrict__ V, const int* __restrict__ lengths,
    float* __restrict__ O)
{
    constexpr int KT = 16;
    __shared__ float sK[KT][DH_];
    __shared__ float sV[KT][DH_];

    const int b = blockIdx.z;
    const int h = blockIdx.y;
    const int tid = threadIdx.x;
    const int qrow = blockIdx.x * 128 + tid;
    const int len = lengths[b];

    // load this thread's q row into registers
    const float* qp = Q + ((size_t)(b * S_ + qrow)) * D_ + h * DH_;
    float qr[DH_];
#pragma unroll
    for (int i = 0; i < DH_ / 4; i++) {
        float4 t = *(const float4*)(qp + i * 4);
        qr[i * 4 + 0] = t.x; qr[i * 4 + 1] = t.y;
        qr[i * 4 + 2] = t.z; qr[i * 4 + 3] = t.w;
    }

    float acc[DH_];
#pragma unroll
    for (int d = 0; d < DH_; d++) acc[d] = 0.f;
    float mrun = -1e30f, lrun = 0.f;

    const int jend = ((len + KT - 1) / KT) * KT;  // cover all valid keys
    const int jj_ld = tid >> 3;  // 0..15  (tile row this thread loads)
    const int c4 = tid & 7;      // 0..7   (float4 column group)

    for (int j0 = 0; j0 < jend; j0 += KT) {
        __syncthreads();
        {
            const float* kp = K + ((size_t)(b * S_ + j0 + jj_ld)) * D_ + h * DH_;
            const float* vp = V + ((size_t)(b * S_ + j0 + jj_ld)) * D_ + h * DH_;
#pragma unroll
            for (int i = 0; i < 2; i++) {
                *(float4*)(&sK[jj_ld][(c4 + 8 * i) * 4]) = *(const float4*)(kp + (c4 + 8 * i) * 4);
                *(float4*)(&sV[jj_ld][(c4 + 8 * i) * 4]) = *(const float4*)(vp + (c4 + 8 * i) * 4);
            }
        }
        __syncthreads();

        // scores for this tile (broadcast smem reads: conflict-free)
        float s[KT];
        float mt = -1e30f;
#pragma unroll
        for (int jj = 0; jj < KT; jj++) {
            float dsum = 0.f;
#pragma unroll
            for (int d = 0; d < DH_; d++)
                dsum = fmaf(qr[d], sK[jj][d], dsum);
            float sc = ((j0 + jj) < len) ? dsum * 0.125f : -1e9f;
            s[jj] = sc;
            mt = fmaxf(mt, sc);
        }

        float mnew = fmaxf(mrun, mt);
        float f = __expf(mrun - mnew);
        lrun *= f;
#pragma unroll
        for (int d = 0; d < DH_; d++) acc[d] *= f;
#pragma unroll
        for (int jj = 0; jj < KT; jj++) {
            float p = __expf(s[jj] - mnew);
            lrun += p;
            s[jj] = p;
        }
#pragma unroll
        for (int jj = 0; jj < KT; jj++) {
#pragma unroll
            for (int d = 0; d < DH_; d++)
                acc[d] = fmaf(s[jj], sV[jj][d], acc[d]);
        }
        mrun = mnew;
    }

    float inv = 1.f / lrun;
    float* op = O + ((size_t)(b * S_ + qrow)) * D_ + h * DH_;
#pragma unroll
    for (int i = 0; i < DH_ / 4; i++) {
        float4 t;
        t.x = acc[i * 4 + 0] * inv; t.y = acc[i * 4 + 1] * inv;
        t.z = acc[i * 4 + 2] * inv; t.w = acc[i * 4 + 3] * inv;
        *(float4*)(op + i * 4) = t;
    }
}

// ---------------------------------------------------------------------------
// Launch
// ---------------------------------------------------------------------------
extern "C" void kernel_launch(void* const* d_in, const int* in_sizes, int n_in,
                              void* d_out, int out_size)
{
    (void)in_sizes; (void)n_in; (void)out_size;
    const float* v       = (const float*)d_in[0];
    const int*   lengths = (const int*)  d_in[1];
    const float* Wq      = (const float*)d_in[2];
    const float* bq      = (const float*)d_in[3];
    const float* Wk      = (const float*)d_in[4];
    const float* bk      = (const float*)d_in[5];
    const float* Wv      = (const float*)d_in[6];
    const float* bv      = (const float*)d_in[7];
    const float* Wo      = (const float*)d_in[8];
    const float* bo      = (const float*)d_in[9];
    float* out = (float*)d_out;

    float *qb, *kb, *vb, *ab;
    cudaGetSymbolAddress((void**)&qb, g_Q);
    cudaGetSymbolAddress((void**)&kb, g_K);
    cudaGetSymbolAddress((void**)&vb, g_V);
    cudaGetSymbolAddress((void**)&ab, g_A);

    const int M = B_ * S_;  // 8192
    dim3 gg(D_ / 128, M / 128);  // (8, 64)

    sgemm_bias<<<gg, 256>>>(v, Wq, bq, qb, M, D_, D_);
    sgemm_bias<<<gg, 256>>>(v, Wk, bk, kb, M, D_, D_);
    sgemm_bias<<<gg, 256>>>(v, Wv, bv, vb, M, D_, D_);

    dim3 ga(S_ / 128, H_, B_);   // (4, 16, 16)
    attn_kernel<<<ga, 128>>>(qb, kb, vb, lengths, ab);

    sgemm_bias<<<gg, 256>>>(ab, Wo, bo, out, M, D_, D_);
}

// round 5
// speedup vs baseline: 2.0276x; 2.0276x over previous
#include <cuda_runtime.h>
#include <cuda_bf16.h>
#include <cstdint>
#include <cstddef>

// Problem constants
#define B_  16
#define S_  512
#define D_  1024
#define H_  16
#define DH_ 64
#define M_  (B_ * S_)   // 8192

// ---------------------------------------------------------------------------
// Scratch (static device globals: allocation-free per harness rules)
// ---------------------------------------------------------------------------
__device__ __align__(128) float g_Q[M_ * D_];
__device__ __align__(128) float g_K[M_ * D_];
__device__ __align__(128) float g_V[M_ * D_];
__device__ __align__(128) float g_A[M_ * D_];
__device__ __align__(128) __nv_bfloat16 g_Ah[M_ * D_];
__device__ __align__(128) __nv_bfloat16 g_Al[M_ * D_];
__device__ __align__(128) __nv_bfloat16 g_Bh[D_ * D_];   // W^T hi  [N][K]
__device__ __align__(128) __nv_bfloat16 g_Bl[D_ * D_];   // W^T lo  [N][K]

// ---------------------------------------------------------------------------
// PTX helpers (sm_80+ features only — the harness lowers via compute_103,
// which rejects all sm_103a-suffixed features like tcgen05/TMA-tensor)
// ---------------------------------------------------------------------------
__device__ __forceinline__ uint32_t smem_u32(const void* p) {
    uint32_t a;
    asm("{ .reg .u64 t; cvta.to.shared.u64 t, %1; cvt.u32.u64 %0, t; }" : "=r"(a) : "l"(p));
    return a;
}
__device__ __forceinline__ void cp16(uint32_t saddr, const void* gaddr) {
    asm volatile("cp.async.cg.shared.global [%0], [%1], 16;" :: "r"(saddr), "l"(gaddr) : "memory");
}
#define CP_COMMIT() asm volatile("cp.async.commit_group;" ::: "memory")
#define CP_WAIT0()  asm volatile("cp.async.wait_group 0;" ::: "memory")
#define CP_WAIT1()  asm volatile("cp.async.wait_group 1;" ::: "memory")

__device__ __forceinline__ void ldsm4(uint32_t* r, uint32_t a) {
    asm volatile("ldmatrix.sync.aligned.m8n8.x4.shared.b16 {%0,%1,%2,%3}, [%4];"
                 : "=r"(r[0]), "=r"(r[1]), "=r"(r[2]), "=r"(r[3]) : "r"(a));
}
__device__ __forceinline__ void mma16816(float* c, const uint32_t* a, const uint32_t* b) {
    asm volatile(
        "mma.sync.aligned.m16n8k16.row.col.f32.bf16.bf16.f32 "
        "{%0,%1,%2,%3}, {%4,%5,%6,%7}, {%8,%9}, {%0,%1,%2,%3};"
        : "+f"(c[0]), "+f"(c[1]), "+f"(c[2]), "+f"(c[3])
        : "r"(a[0]), "r"(a[1]), "r"(a[2]), "r"(a[3]), "r"(b[0]), "r"(b[1]));
}

// 128B-row swizzle (bank-conflict-free ldmatrix)
#define SMEM_SWZ(o) ((o) ^ (((o) >> 3) & 0x70))

// ---------------------------------------------------------------------------
// HMMA GEMM: C[8192,1024] = Ah@Bh^T + Ah@Bl^T + Al@Bh^T + bias
// CTA tile 128x128, BK=64 (128B rows), 2-stage cp.async pipeline.
// 8 warps (2x4), warp tile 64x32.  grid (8, 64), 256 threads.
// ---------------------------------------------------------------------------
#define T_AH 0
#define T_AL 16384
#define T_BH 32768
#define T_BL 49152
#define STAGE_BYTES 65536
#define GEMM_SMEM (2 * STAGE_BYTES)   // 131072

__device__ __forceinline__ void load_tile16(uint32_t sdst, const __nv_bfloat16* g,
                                            int row0, int kc, int tid) {
#pragma unroll
    for (int i = 0; i < 4; i++) {
        int idx = tid + i * 256;
        int r = idx >> 3, c = idx & 7;
        const __nv_bfloat16* gp = g + (size_t)(row0 + r) * D_ + kc * 64 + c * 8;
        cp16(sdst + SMEM_SWZ(r * 128 + c * 16), gp);
    }
}

__global__ __launch_bounds__(256) void gemm_mma(
    const __nv_bfloat16* __restrict__ Ah, const __nv_bfloat16* __restrict__ Al,
    const __nv_bfloat16* __restrict__ Bh, const __nv_bfloat16* __restrict__ Bl,
    const float* __restrict__ bias, float* __restrict__ C)
{
    extern __shared__ __align__(1024) char smem[];
    const int tid  = threadIdx.x;
    const int wid  = tid >> 5, lane = tid & 31;
    const int m0   = blockIdx.y * 128;
    const int n0   = blockIdx.x * 128;
    const int wm   = (wid >> 2) * 64;   // warp row offset in tile: 0 / 64
    const int wn   = (wid & 3)  * 32;   // warp col offset in tile: 0/32/64/96
    uint32_t sb = smem_u32(smem);

    float acc[4][4][4];
#pragma unroll
    for (int i = 0; i < 4; i++)
#pragma unroll
        for (int j = 0; j < 4; j++)
#pragma unroll
            for (int k = 0; k < 4; k++) acc[i][j][k] = 0.f;

    // ldmatrix lane addressing (byte offsets within a tile, pre-swizzle)
    const int a_row = wm + (lane & 15);
    const int a_coff = (lane >> 4) * 16;              // 16B chunk select
    const int b_row = wn + ((lane >> 4) << 3) + (lane & 7);
    const int b_coff = ((lane >> 3) & 1) * 16;

    // prologue: chunk 0 -> stage 0
    load_tile16(sb + T_AH, Ah, m0, 0, tid);
    load_tile16(sb + T_AL, Al, m0, 0, tid);
    load_tile16(sb + T_BH, Bh, n0, 0, tid);
    load_tile16(sb + T_BL, Bl, n0, 0, tid);
    CP_COMMIT();

#pragma unroll 1
    for (int c = 0; c < 16; c++) {
        const int s = c & 1, ns = s ^ 1;

        if (c + 1 < 16) {
            uint32_t so = sb + ns * STAGE_BYTES;
            load_tile16(so + T_AH, Ah, m0, c + 1, tid);
            load_tile16(so + T_AL, Al, m0, c + 1, tid);
            load_tile16(so + T_BH, Bh, n0, c + 1, tid);
            load_tile16(so + T_BL, Bl, n0, c + 1, tid);
            CP_COMMIT();
            CP_WAIT1();
        } else {
            CP_WAIT0();
        }
        __syncthreads();

        const uint32_t so = sb + s * STAGE_BYTES;
#pragma unroll
        for (int ks = 0; ks < 4; ks++) {
            const int kb = ks * 32;   // byte col of this k16 step
            uint32_t ah[4][4], al[4][4], bh[2][4], bl[2][4];
#pragma unroll
            for (int mt = 0; mt < 4; mt++) {
                uint32_t off = SMEM_SWZ((a_row + mt * 16) * 128 + kb + a_coff);
                ldsm4(ah[mt], so + T_AH + off);
                ldsm4(al[mt], so + T_AL + off);
            }
#pragma unroll
            for (int nt2 = 0; nt2 < 2; nt2++) {
                uint32_t off = SMEM_SWZ((b_row + nt2 * 16) * 128 + kb + b_coff);
                ldsm4(bh[nt2], so + T_BH + off);
                ldsm4(bl[nt2], so + T_BL + off);
            }
#pragma unroll
            for (int mt = 0; mt < 4; mt++) {
#pragma unroll
                for (int nt = 0; nt < 4; nt++) {
                    const uint32_t* fbh = &bh[nt >> 1][(nt & 1) * 2];
                    const uint32_t* fbl = &bl[nt >> 1][(nt & 1) * 2];
                    mma16816(acc[mt][nt], ah[mt], fbh);
                    mma16816(acc[mt][nt], ah[mt], fbl);
                    mma16816(acc[mt][nt], al[mt], fbh);
                }
            }
        }
        __syncthreads();
    }

    // epilogue: lane T owns rows (T/4, T/4+8), cols 2*(T%4)+{0,1} of each 16x8 frag
    const int er = lane >> 2;
    const int ec = (lane & 3) * 2;
#pragma unroll
    for (int mt = 0; mt < 4; mt++) {
#pragma unroll
        for (int nt = 0; nt < 4; nt++) {
            int row = m0 + wm + mt * 16 + er;
            int col = n0 + wn + nt * 8 + ec;
            float b0 = bias[col], b1 = bias[col + 1];
            float2 o0, o1;
            o0.x = acc[mt][nt][0] + b0; o0.y = acc[mt][nt][1] + b1;
            o1.x = acc[mt][nt][2] + b0; o1.y = acc[mt][nt][3] + b1;
            *(float2*)(C + (size_t)row * D_ + col) = o0;
            *(float2*)(C + (size_t)(row + 8) * D_ + col) = o1;
        }
    }
}

// ---------------------------------------------------------------------------
// fp32 -> split bf16 (hi + lo)
// ---------------------------------------------------------------------------
__global__ __launch_bounds__(256) void split_bf16_kernel(
    const float4* __restrict__ x, __nv_bfloat162* __restrict__ hi,
    __nv_bfloat162* __restrict__ lo, int n4)
{
    int i = blockIdx.x * blockDim.x + threadIdx.x;
    if (i >= n4) return;
    float4 v = x[i];
    __nv_bfloat16 h0 = __float2bfloat16(v.x), h1 = __float2bfloat16(v.y);
    __nv_bfloat16 h2 = __float2bfloat16(v.z), h3 = __float2bfloat16(v.w);
    __nv_bfloat16 l0 = __float2bfloat16(v.x - __bfloat162float(h0));
    __nv_bfloat16 l1 = __float2bfloat16(v.y - __bfloat162float(h1));
    __nv_bfloat16 l2 = __float2bfloat16(v.z - __bfloat162float(h2));
    __nv_bfloat16 l3 = __float2bfloat16(v.w - __bfloat162float(h3));
    __nv_bfloat162 a; a.x = h0; a.y = h1; hi[2 * i] = a;
    __nv_bfloat162 b; b.x = h2; b.y = h3; hi[2 * i + 1] = b;
    __nv_bfloat162 c; c.x = l0; c.y = l1; lo[2 * i] = c;
    __nv_bfloat162 d; d.x = l2; d.y = l3; lo[2 * i + 1] = d;
}

// ---------------------------------------------------------------------------
// W[K,N] fp32 -> W^T[N,K] split bf16   grid (32,32), block (32,8)
// ---------------------------------------------------------------------------
__global__ __launch_bounds__(256) void transpose_split(
    const float* __restrict__ W, __nv_bfloat16* __restrict__ Th,
    __nv_bfloat16* __restrict__ Tl)
{
    __shared__ float t[32][33];
    const int n0 = blockIdx.x * 32, k0 = blockIdx.y * 32;
    const int tx = threadIdx.x, ty = threadIdx.y;
#pragma unroll
    for (int i = 0; i < 4; i++)
        t[ty + i * 8][tx] = W[(size_t)(k0 + ty + i * 8) * D_ + n0 + tx];
    __syncthreads();
#pragma unroll
    for (int i = 0; i < 4; i++) {
        int n = n0 + ty + i * 8;
        float v = t[tx][ty + i * 8];
        __nv_bfloat16 h = __float2bfloat16(v);
        __nv_bfloat16 l = __float2bfloat16(v - __bfloat162float(h));
        Th[(size_t)n * D_ + k0 + tx] = h;
        Tl[(size_t)n * D_ + k0 + tx] = l;
    }
}

// ---------------------------------------------------------------------------
// Flash attention, fp32 (float4-vectorized smem reads)
// ---------------------------------------------------------------------------
__global__ __launch_bounds__(128) void attn_kernel(
    const float* __restrict__ Q, const float* __restrict__ K,
    const float* __restrict__ V, const int* __restrict__ lengths,
    float* __restrict__ O)
{
    constexpr int KT = 16;
    __shared__ float sK[KT][DH_];
    __shared__ float sV[KT][DH_];

    const int b = blockIdx.z;
    const int h = blockIdx.y;
    const int tid = threadIdx.x;
    const int qrow = blockIdx.x * 128 + tid;
    const int len = lengths[b];

    const float* qp = Q + ((size_t)(b * S_ + qrow)) * D_ + h * DH_;
    float4 qr[DH_ / 4];
#pragma unroll
    for (int i = 0; i < DH_ / 4; i++) qr[i] = *(const float4*)(qp + i * 4);

    float4 acc[DH_ / 4];
#pragma unroll
    for (int i = 0; i < DH_ / 4; i++) acc[i] = make_float4(0.f, 0.f, 0.f, 0.f);
    float mrun = -1e30f, lrun = 0.f;

    const int jend = ((len + KT - 1) / KT) * KT;
    const int jj_ld = tid >> 3;
    const int c4 = tid & 7;

    for (int j0 = 0; j0 < jend; j0 += KT) {
        __syncthreads();
        {
            const float* kp = K + ((size_t)(b * S_ + j0 + jj_ld)) * D_ + h * DH_;
            const float* vp = V + ((size_t)(b * S_ + j0 + jj_ld)) * D_ + h * DH_;
#pragma unroll
            for (int i = 0; i < 2; i++) {
                *(float4*)(&sK[jj_ld][(c4 + 8 * i) * 4]) = *(const float4*)(kp + (c4 + 8 * i) * 4);
                *(float4*)(&sV[jj_ld][(c4 + 8 * i) * 4]) = *(const float4*)(vp + (c4 + 8 * i) * 4);
            }
        }
        __syncthreads();

        float s[KT];
        float mt = -1e30f;
#pragma unroll
        for (int jj = 0; jj < KT; jj++) {
            const float4* kp4 = (const float4*)sK[jj];
            float dsum = 0.f;
#pragma unroll
            for (int i = 0; i < DH_ / 4; i++) {
                float4 kk = kp4[i];
                dsum = fmaf(qr[i].x, kk.x, dsum);
                dsum = fmaf(qr[i].y, kk.y, dsum);
                dsum = fmaf(qr[i].z, kk.z, dsum);
                dsum = fmaf(qr[i].w, kk.w, dsum);
            }
            float sc = ((j0 + jj) < len) ? dsum * 0.125f : -1e9f;
            s[jj] = sc;
            mt = fmaxf(mt, sc);
        }

        float mnew = fmaxf(mrun, mt);
        float f = __expf(mrun - mnew);
        lrun *= f;
#pragma unroll
        for (int i = 0; i < DH_ / 4; i++) {
            acc[i].x *= f; acc[i].y *= f; acc[i].z *= f; acc[i].w *= f;
        }
#pragma unroll
        for (int jj = 0; jj < KT; jj++) {
            float p = __expf(s[jj] - mnew);
            lrun += p;
            s[jj] = p;
        }
#pragma unroll
        for (int jj = 0; jj < KT; jj++) {
            const float4* vp4 = (const float4*)sV[jj];
            float p = s[jj];
#pragma unroll
            for (int i = 0; i < DH_ / 4; i++) {
                float4 vv = vp4[i];
                acc[i].x = fmaf(p, vv.x, acc[i].x);
                acc[i].y = fmaf(p, vv.y, acc[i].y);
                acc[i].z = fmaf(p, vv.z, acc[i].z);
                acc[i].w = fmaf(p, vv.w, acc[i].w);
            }
        }
        mrun = mnew;
    }

    float inv = 1.f / lrun;
    float* op = O + ((size_t)(b * S_ + qrow)) * D_ + h * DH_;
#pragma unroll
    for (int i = 0; i < DH_ / 4; i++) {
        float4 t;
        t.x = acc[i].x * inv; t.y = acc[i].y * inv;
        t.z = acc[i].z * inv; t.w = acc[i].w * inv;
        *(float4*)(op + i * 4) = t;
    }
}

// ---------------------------------------------------------------------------
// Launch
// ---------------------------------------------------------------------------
extern "C" void kernel_launch(void* const* d_in, const int* in_sizes, int n_in,
                              void* d_out, int out_size)
{
    (void)in_sizes; (void)n_in; (void)out_size;
    const float* v       = (const float*)d_in[0];
    const int*   lengths = (const int*)  d_in[1];
    const float* Wq      = (const float*)d_in[2];
    const float* bq      = (const float*)d_in[3];
    const float* Wk      = (const float*)d_in[4];
    const float* bk      = (const float*)d_in[5];
    const float* Wv      = (const float*)d_in[6];
    const float* bv      = (const float*)d_in[7];
    const float* Wo      = (const float*)d_in[8];
    const float* bo      = (const float*)d_in[9];
    float* out = (float*)d_out;

    float *qb, *kb, *vb, *ab;
    __nv_bfloat16 *ah, *al, *bh, *bl;
    cudaGetSymbolAddress((void**)&qb, g_Q);
    cudaGetSymbolAddress((void**)&kb, g_K);
    cudaGetSymbolAddress((void**)&vb, g_V);
    cudaGetSymbolAddress((void**)&ab, g_A);
    cudaGetSymbolAddress((void**)&ah, g_Ah);
    cudaGetSymbolAddress((void**)&al, g_Al);
    cudaGetSymbolAddress((void**)&bh, g_Bh);
    cudaGetSymbolAddress((void**)&bl, g_Bl);

    cudaFuncSetAttribute(gemm_mma, cudaFuncAttributeMaxDynamicSharedMemorySize, GEMM_SMEM);

    const int n4 = M_ * D_ / 4;                 // 2M float4
    dim3 gsplit((n4 + 255) / 256);
    dim3 gtr(32, 32), btr(32, 8);
    dim3 gg(D_ / 128, M_ / 128);                // (8, 64)

    // v -> split bf16 once (shared by Q/K/V projections)
    split_bf16_kernel<<<gsplit, 256>>>((const float4*)v,
        (__nv_bfloat162*)ah, (__nv_bfloat162*)al, n4);

    transpose_split<<<gtr, btr>>>(Wq, bh, bl);
    gemm_mma<<<gg, 256, GEMM_SMEM>>>(ah, al, bh, bl, bq, qb);
    transpose_split<<<gtr, btr>>>(Wk, bh, bl);
    gemm_mma<<<gg, 256, GEMM_SMEM>>>(ah, al, bh, bl, bk, kb);
    transpose_split<<<gtr, btr>>>(Wv, bh, bl);
    gemm_mma<<<gg, 256, GEMM_SMEM>>>(ah, al, bh, bl, bv, vb);

    dim3 ga(S_ / 128, H_, B_);                  // (4, 16, 16)
    attn_kernel<<<ga, 128>>>(qb, kb, vb, lengths, ab);

    split_bf16_kernel<<<gsplit, 256>>>((const float4*)ab,
        (__nv_bfloat162*)ah, (__nv_bfloat162*)al, n4);
    transpose_split<<<gtr, btr>>>(Wo, bh, bl);
    gemm_mma<<<gg, 256, GEMM_SMEM>>>(ah, al, bh, bl, bo, out);
}

// round 6
// speedup vs baseline: 2.9539x; 1.4568x over previous
#include <cuda_runtime.h>
#include <cuda_bf16.h>
#include <cstdint>
#include <cstddef>

// Problem constants
#define B_  16
#define S_  512
#define D_  1024
#define H_  16
#define DH_ 64
#define M_  (B_ * S_)   // 8192

// ---------------------------------------------------------------------------
// Scratch (static device globals)
// ---------------------------------------------------------------------------
__device__ __align__(128) __nv_bfloat16 g_Ah[M_ * D_];   // v-split, later attn out (row-major)
__device__ __align__(128) __nv_bfloat16 g_Al[M_ * D_];
__device__ __align__(128) __nv_bfloat16 g_Bh[D_ * D_];   // W^T hi  [N][K]
__device__ __align__(128) __nv_bfloat16 g_Bl[D_ * D_];
__device__ __align__(128) __nv_bfloat16 g_Qh[M_ * D_];   // head-major [b,h,s,dh]
__device__ __align__(128) __nv_bfloat16 g_Ql[M_ * D_];
__device__ __align__(128) __nv_bfloat16 g_Kh[M_ * D_];
__device__ __align__(128) __nv_bfloat16 g_Kl[M_ * D_];
__device__ __align__(128) __nv_bfloat16 g_Vh[M_ * D_];
__device__ __align__(128) __nv_bfloat16 g_Vl[M_ * D_];

// ---------------------------------------------------------------------------
// PTX helpers (sm_80+ features only; compute_103 lowering rejects sm_103a-only)
// ---------------------------------------------------------------------------
__device__ __forceinline__ uint32_t smem_u32(const void* p) {
    uint32_t a;
    asm("{ .reg .u64 t; cvta.to.shared.u64 t, %1; cvt.u32.u64 %0, t; }" : "=r"(a) : "l"(p));
    return a;
}
__device__ __forceinline__ void cp16(uint32_t saddr, const void* gaddr) {
    asm volatile("cp.async.cg.shared.global [%0], [%1], 16;" :: "r"(saddr), "l"(gaddr) : "memory");
}
#define CP_COMMIT() asm volatile("cp.async.commit_group;" ::: "memory")
#define CP_WAIT0()  asm volatile("cp.async.wait_group 0;" ::: "memory")
#define CP_WAIT1()  asm volatile("cp.async.wait_group 1;" ::: "memory")

__device__ __forceinline__ void ldsm4(uint32_t* r, uint32_t a) {
    asm volatile("ldmatrix.sync.aligned.m8n8.x4.shared.b16 {%0,%1,%2,%3}, [%4];"
                 : "=r"(r[0]), "=r"(r[1]), "=r"(r[2]), "=r"(r[3]) : "r"(a));
}
__device__ __forceinline__ void ldsm4t(uint32_t* r, uint32_t a) {
    asm volatile("ldmatrix.sync.aligned.m8n8.x4.trans.shared.b16 {%0,%1,%2,%3}, [%4];"
                 : "=r"(r[0]), "=r"(r[1]), "=r"(r[2]), "=r"(r[3]) : "r"(a));
}
__device__ __forceinline__ void mma16816(float* c, const uint32_t* a, const uint32_t* b) {
    asm volatile(
        "mma.sync.aligned.m16n8k16.row.col.f32.bf16.bf16.f32 "
        "{%0,%1,%2,%3}, {%4,%5,%6,%7}, {%8,%9}, {%0,%1,%2,%3};"
        : "+f"(c[0]), "+f"(c[1]), "+f"(c[2]), "+f"(c[3])
        : "r"(a[0]), "r"(a[1]), "r"(a[2]), "r"(a[3]), "r"(b[0]), "r"(b[1]));
}

#define SMEM_SWZ(o) ((o) ^ (((o) >> 3) & 0x70))

// ---------------------------------------------------------------------------
// HMMA GEMM: C = Ah@Bh^T + Ah@Bl^T + Al@Bh^T (+bias)
// MODE 0: fp32 row-major C.  MODE 1: split bf16 head-major [b,h,s,dh].
// CTA tile 128x128, BK=64, 2-stage cp.async; 8 warps 2x4, warp tile 64x32.
// ---------------------------------------------------------------------------
#define T_AH 0
#define T_AL 16384
#define T_BH 32768
#define T_BL 49152
#define STAGE_BYTES 65536
#define GEMM_SMEM (2 * STAGE_BYTES)

__device__ __forceinline__ void load_tile16(uint32_t sdst, const __nv_bfloat16* g,
                                            int row0, int kc, int tid) {
#pragma unroll
    for (int i = 0; i < 4; i++) {
        int idx = tid + i * 256;
        int r = idx >> 3, c = idx & 7;
        const __nv_bfloat16* gp = g + (size_t)(row0 + r) * D_ + kc * 64 + c * 8;
        cp16(sdst + SMEM_SWZ(r * 128 + c * 16), gp);
    }
}

template <int MODE>
__global__ __launch_bounds__(256) void gemm_mma(
    const __nv_bfloat16* __restrict__ Ah, const __nv_bfloat16* __restrict__ Al,
    const __nv_bfloat16* __restrict__ Bh, const __nv_bfloat16* __restrict__ Bl,
    const float* __restrict__ bias, float* __restrict__ C,
    __nv_bfloat16* __restrict__ Ch, __nv_bfloat16* __restrict__ Cl)
{
    extern __shared__ __align__(1024) char smem[];
    const int tid  = threadIdx.x;
    const int wid  = tid >> 5, lane = tid & 31;
    const int m0   = blockIdx.y * 128;
    const int n0   = blockIdx.x * 128;
    const int wm   = (wid >> 2) * 64;
    const int wn   = (wid & 3)  * 32;
    uint32_t sb = smem_u32(smem);

    float acc[4][4][4];
#pragma unroll
    for (int i = 0; i < 4; i++)
#pragma unroll
        for (int j = 0; j < 4; j++)
#pragma unroll
            for (int k = 0; k < 4; k++) acc[i][j][k] = 0.f;

    const int a_row = wm + (lane & 15);
    const int a_coff = (lane >> 4) * 16;
    const int b_row = wn + ((lane >> 4) << 3) + (lane & 7);
    const int b_coff = ((lane >> 3) & 1) * 16;

    load_tile16(sb + T_AH, Ah, m0, 0, tid);
    load_tile16(sb + T_AL, Al, m0, 0, tid);
    load_tile16(sb + T_BH, Bh, n0, 0, tid);
    load_tile16(sb + T_BL, Bl, n0, 0, tid);
    CP_COMMIT();

#pragma unroll 1
    for (int c = 0; c < 16; c++) {
        const int s = c & 1, ns = s ^ 1;

        if (c + 1 < 16) {
            uint32_t so = sb + ns * STAGE_BYTES;
            load_tile16(so + T_AH, Ah, m0, c + 1, tid);
            load_tile16(so + T_AL, Al, m0, c + 1, tid);
            load_tile16(so + T_BH, Bh, n0, c + 1, tid);
            load_tile16(so + T_BL, Bl, n0, c + 1, tid);
            CP_COMMIT();
            CP_WAIT1();
        } else {
            CP_WAIT0();
        }
        __syncthreads();

        const uint32_t so = sb + s * STAGE_BYTES;
#pragma unroll
        for (int ks = 0; ks < 4; ks++) {
            const int kb = ks * 32;
            uint32_t ah[4][4], al[4][4], bh[2][4], bl[2][4];
#pragma unroll
            for (int mt = 0; mt < 4; mt++) {
                uint32_t off = SMEM_SWZ((a_row + mt * 16) * 128 + kb + a_coff);
                ldsm4(ah[mt], so + T_AH + off);
                ldsm4(al[mt], so + T_AL + off);
            }
#pragma unroll
            for (int nt2 = 0; nt2 < 2; nt2++) {
                uint32_t off = SMEM_SWZ((b_row + nt2 * 16) * 128 + kb + b_coff);
                ldsm4(bh[nt2], so + T_BH + off);
                ldsm4(bl[nt2], so + T_BL + off);
            }
#pragma unroll
            for (int mt = 0; mt < 4; mt++) {
#pragma unroll
                for (int nt = 0; nt < 4; nt++) {
                    const uint32_t* fbh = &bh[nt >> 1][(nt & 1) * 2];
                    const uint32_t* fbl = &bl[nt >> 1][(nt & 1) * 2];
                    mma16816(acc[mt][nt], ah[mt], fbh);
                    mma16816(acc[mt][nt], ah[mt], fbl);
                    mma16816(acc[mt][nt], al[mt], fbh);
                }
            }
        }
        __syncthreads();
    }

    const int er = lane >> 2;
    const int ec = (lane & 3) * 2;
#pragma unroll
    for (int mt = 0; mt < 4; mt++) {
#pragma unroll
        for (int nt = 0; nt < 4; nt++) {
            int row = m0 + wm + mt * 16 + er;
            int col = n0 + wn + nt * 8 + ec;
            float b0 = bias[col], b1 = bias[col + 1];
            float o0 = acc[mt][nt][0] + b0, o1 = acc[mt][nt][1] + b1;
            float o2 = acc[mt][nt][2] + b0, o3 = acc[mt][nt][3] + b1;
            if (MODE == 0) {
                float2 p0 = make_float2(o0, o1), p1 = make_float2(o2, o3);
                *(float2*)(C + (size_t)row * D_ + col) = p0;
                *(float2*)(C + (size_t)(row + 8) * D_ + col) = p1;
            } else {
                int bb = row >> 9, ss = row & 511, hh = col >> 6, dd = col & 63;
                size_t base = (((size_t)bb * H_ + hh) * S_ + ss) * DH_ + dd;
                __nv_bfloat162 hp = __floats2bfloat162_rn(o0, o1);
                float2 hf = __bfloat1622float2(hp);
                __nv_bfloat162 lp = __floats2bfloat162_rn(o0 - hf.x, o1 - hf.y);
                *(__nv_bfloat162*)(Ch + base) = hp;
                *(__nv_bfloat162*)(Cl + base) = lp;
                __nv_bfloat162 hp2 = __floats2bfloat162_rn(o2, o3);
                float2 hf2 = __bfloat1622float2(hp2);
                __nv_bfloat162 lp2 = __floats2bfloat162_rn(o2 - hf2.x, o3 - hf2.y);
                *(__nv_bfloat162*)(Ch + base + 8 * DH_) = hp2;
                *(__nv_bfloat162*)(Cl + base + 8 * DH_) = lp2;
            }
        }
    }
}

// ---------------------------------------------------------------------------
// HMMA flash attention.
// CTA = one (b,h) x 128 q rows. 8 warps x 16 rows. 64-key tiles, 2-stage.
// 3-term split everywhere: QhKh+QhKl+QlKh ; PhVh+PhVl+PlVh.
// Writes split bf16 row-major [M][D] for the O projection.
// ---------------------------------------------------------------------------
#define AQ_H 0
#define AQ_L 16384
#define AST  32768
#define AK_H 0
#define AK_L 8192
#define AV_H 16384
#define AV_L 24576
#define AST_BYTES 32768
#define ATTN_SMEM (32768 + 2 * AST_BYTES)   // 98304

__global__ __launch_bounds__(256) void attn_mma(
    const __nv_bfloat16* __restrict__ Qh_, const __nv_bfloat16* __restrict__ Ql_,
    const __nv_bfloat16* __restrict__ Kh_, const __nv_bfloat16* __restrict__ Kl_,
    const __nv_bfloat16* __restrict__ Vh_, const __nv_bfloat16* __restrict__ Vl_,
    const int* __restrict__ lengths,
    __nv_bfloat16* __restrict__ Oh_, __nv_bfloat16* __restrict__ Ol_)
{
    extern __shared__ __align__(1024) char smem[];
    const int tid = threadIdx.x, wid = tid >> 5, lane = tid & 31;
    const int b = blockIdx.z, h = blockIdx.y, q0 = blockIdx.x * 128;
    const int len = lengths[b];
    uint32_t sb = smem_u32(smem);
    const size_t bh_off = ((size_t)b * H_ + h) * (S_ * DH_);

    // Q tile load (128 rows x 128B, hi+lo)
#pragma unroll
    for (int i = 0; i < 4; i++) {
        int idx = tid + i * 256;
        int r = idx >> 3, c = idx & 7;
        cp16(sb + AQ_H + SMEM_SWZ(r * 128 + c * 16), Qh_ + bh_off + (size_t)(q0 + r) * DH_ + c * 8);
        cp16(sb + AQ_L + SMEM_SWZ(r * 128 + c * 16), Ql_ + bh_off + (size_t)(q0 + r) * DH_ + c * 8);
    }
    CP_COMMIT();

    const int jend = (len + 63) & ~63;     // <= 512
    const int ntile = jend >> 6;

    // prefetch KV tile 0 -> stage 0
    {
        uint32_t so = sb + AST;
#pragma unroll
        for (int i = 0; i < 2; i++) {
            int idx = tid + i * 256;
            int r = idx >> 3, c = idx & 7;
            size_t g = bh_off + (size_t)r * DH_ + c * 8;
            uint32_t sw = SMEM_SWZ(r * 128 + c * 16);
            cp16(so + AK_H + sw, Kh_ + g);
            cp16(so + AK_L + sw, Kl_ + g);
            cp16(so + AV_H + sw, Vh_ + g);
            cp16(so + AV_L + sw, Vl_ + g);
        }
        CP_COMMIT();
    }

    // wait for Q (KV0 may still fly), then pull Q fragments
    CP_WAIT1();
    __syncthreads();

    const int a_row = wid * 16 + (lane & 15);
    const int a_co = (lane >> 4) * 16;
    uint32_t qh[4][4], ql[4][4];
#pragma unroll
    for (int s = 0; s < 4; s++) {
        uint32_t off = SMEM_SWZ(a_row * 128 + s * 32 + a_co);
        ldsm4(qh[s], sb + AQ_H + off);
        ldsm4(ql[s], sb + AQ_L + off);
    }

    float oa[8][4];
#pragma unroll
    for (int i = 0; i < 8; i++)
#pragma unroll
        for (int j = 0; j < 4; j++) oa[i][j] = 0.f;
    float m0 = -1e30f, m1 = -1e30f, l0 = 0.f, l1 = 0.f;

    const int krow = ((lane >> 4) << 3) + (lane & 7);   // K ldsm pattern (gemm-B)
    const int kco  = ((lane >> 3) & 1) * 16;
    const int vrow = lane & 15;                          // V trans ldsm pattern
    const int vco  = (lane >> 4) * 16;

#pragma unroll 1
    for (int t = 0; t < ntile; t++) {
        CP_WAIT0();
        __syncthreads();
        if (t + 1 < ntile) {
            uint32_t so = sb + AST + ((t + 1) & 1) * AST_BYTES;
            int j0n = (t + 1) * 64;
#pragma unroll
            for (int i = 0; i < 2; i++) {
                int idx = tid + i * 256;
                int r = idx >> 3, c = idx & 7;
                size_t g = bh_off + (size_t)(j0n + r) * DH_ + c * 8;
                uint32_t sw = SMEM_SWZ(r * 128 + c * 16);
                cp16(so + AK_H + sw, Kh_ + g);
                cp16(so + AK_L + sw, Kl_ + g);
                cp16(so + AV_H + sw, Vh_ + g);
                cp16(so + AV_L + sw, Vl_ + g);
            }
            CP_COMMIT();
        }

        const uint32_t so = sb + AST + (t & 1) * AST_BYTES;
        const int j0 = t * 64;

        // ---- S = Q @ K^T (3-term split) ----
        float S[8][4];
#pragma unroll
        for (int i = 0; i < 8; i++)
#pragma unroll
            for (int j = 0; j < 4; j++) S[i][j] = 0.f;
#pragma unroll
        for (int s = 0; s < 4; s++) {
#pragma unroll
            for (int g = 0; g < 4; g++) {
                uint32_t kh4[4], kl4[4];
                uint32_t off = SMEM_SWZ((g * 16 + krow) * 128 + s * 32 + kco);
                ldsm4(kh4, so + AK_H + off);
                ldsm4(kl4, so + AK_L + off);
                mma16816(S[2 * g],     qh[s], kh4);
                mma16816(S[2 * g],     qh[s], kl4);
                mma16816(S[2 * g],     ql[s], kh4);
                mma16816(S[2 * g + 1], qh[s], kh4 + 2);
                mma16816(S[2 * g + 1], qh[s], kl4 + 2);
                mma16816(S[2 * g + 1], ql[s], kh4 + 2);
            }
        }

        // ---- scale + mask ----
        if (j0 + 64 > len) {
            int kb0 = j0 + 2 * (lane & 3);
#pragma unroll
            for (int j = 0; j < 8; j++) {
#pragma unroll
                for (int e = 0; e < 4; e++) {
                    int kk = kb0 + 8 * j + (e & 1);
                    S[j][e] = (kk < len) ? S[j][e] * 0.125f : -1e9f;
                }
            }
        } else {
#pragma unroll
            for (int j = 0; j < 8; j++)
#pragma unroll
                for (int e = 0; e < 4; e++) S[j][e] *= 0.125f;
        }

        // ---- online softmax ----
        float mx0 = -1e30f, mx1 = -1e30f;
#pragma unroll
        for (int j = 0; j < 8; j++) {
            mx0 = fmaxf(mx0, fmaxf(S[j][0], S[j][1]));
            mx1 = fmaxf(mx1, fmaxf(S[j][2], S[j][3]));
        }
        mx0 = fmaxf(mx0, __shfl_xor_sync(0xffffffffu, mx0, 1));
        mx0 = fmaxf(mx0, __shfl_xor_sync(0xffffffffu, mx0, 2));
        mx1 = fmaxf(mx1, __shfl_xor_sync(0xffffffffu, mx1, 1));
        mx1 = fmaxf(mx1, __shfl_xor_sync(0xffffffffu, mx1, 2));
        float mn0 = fmaxf(m0, mx0), mn1 = fmaxf(m1, mx1);
        float f0 = __expf(m0 - mn0), f1 = __expf(m1 - mn1);
        l0 *= f0; l1 *= f1;
#pragma unroll
        for (int i = 0; i < 8; i++) {
            oa[i][0] *= f0; oa[i][1] *= f0; oa[i][2] *= f1; oa[i][3] *= f1;
        }
        float rs0 = 0.f, rs1 = 0.f;
#pragma unroll
        for (int j = 0; j < 8; j++) {
            S[j][0] = __expf(S[j][0] - mn0);
            S[j][1] = __expf(S[j][1] - mn0);
            S[j][2] = __expf(S[j][2] - mn1);
            S[j][3] = __expf(S[j][3] - mn1);
            rs0 += S[j][0] + S[j][1];
            rs1 += S[j][2] + S[j][3];
        }
        rs0 += __shfl_xor_sync(0xffffffffu, rs0, 1);
        rs0 += __shfl_xor_sync(0xffffffffu, rs0, 2);
        rs1 += __shfl_xor_sync(0xffffffffu, rs1, 1);
        rs1 += __shfl_xor_sync(0xffffffffu, rs1, 2);
        l0 += rs0; l1 += rs1;
        m0 = mn0; m1 = mn1;

        // ---- O += P @ V (3-term split) ----
#pragma unroll
        for (int s = 0; s < 4; s++) {
            uint32_t pah[4], pal[4];
#pragma unroll
            for (int half = 0; half < 2; half++) {
                const float* Sf = S[2 * s + half];
                __nv_bfloat162 hp0 = __floats2bfloat162_rn(Sf[0], Sf[1]);
                float2 hf0 = __bfloat1622float2(hp0);
                __nv_bfloat162 lp0 = __floats2bfloat162_rn(Sf[0] - hf0.x, Sf[1] - hf0.y);
                __nv_bfloat162 hp1 = __floats2bfloat162_rn(Sf[2], Sf[3]);
                float2 hf1 = __bfloat1622float2(hp1);
                __nv_bfloat162 lp1 = __floats2bfloat162_rn(Sf[2] - hf1.x, Sf[3] - hf1.y);
                pah[2 * half]     = *(uint32_t*)&hp0;
                pah[2 * half + 1] = *(uint32_t*)&hp1;
                pal[2 * half]     = *(uint32_t*)&lp0;
                pal[2 * half + 1] = *(uint32_t*)&lp1;
            }
#pragma unroll
            for (int g = 0; g < 4; g++) {
                uint32_t vh4[4], vl4[4];
                uint32_t off = SMEM_SWZ((s * 16 + vrow) * 128 + g * 32 + vco);
                ldsm4t(vh4, so + AV_H + off);
                ldsm4t(vl4, so + AV_L + off);
                mma16816(oa[2 * g],     pah, vh4);
                mma16816(oa[2 * g],     pah, vl4);
                mma16816(oa[2 * g],     pal, vh4);
                mma16816(oa[2 * g + 1], pah, vh4 + 2);
                mma16816(oa[2 * g + 1], pah, vl4 + 2);
                mma16816(oa[2 * g + 1], pal, vh4 + 2);
            }
        }
    }

    // ---- epilogue: normalize, split, write row-major [M][D] ----
    float il0 = 1.f / l0, il1 = 1.f / l1;
    int qrow = q0 + wid * 16 + (lane >> 2);
    size_t base0 = ((size_t)b * S_ + qrow) * D_ + h * DH_ + 2 * (lane & 3);
    size_t base1 = base0 + (size_t)8 * D_;
#pragma unroll
    for (int nf = 0; nf < 8; nf++) {
        float e0 = oa[nf][0] * il0, e1 = oa[nf][1] * il0;
        float e2 = oa[nf][2] * il1, e3 = oa[nf][3] * il1;
        __nv_bfloat162 hp0 = __floats2bfloat162_rn(e0, e1);
        float2 hf0 = __bfloat1622float2(hp0);
        __nv_bfloat162 lp0 = __floats2bfloat162_rn(e0 - hf0.x, e1 - hf0.y);
        __nv_bfloat162 hp1 = __floats2bfloat162_rn(e2, e3);
        float2 hf1 = __bfloat1622float2(hp1);
        __nv_bfloat162 lp1 = __floats2bfloat162_rn(e2 - hf1.x, e3 - hf1.y);
        *(__nv_bfloat162*)(Oh_ + base0 + 8 * nf) = hp0;
        *(__nv_bfloat162*)(Ol_ + base0 + 8 * nf) = lp0;
        *(__nv_bfloat162*)(Oh_ + base1 + 8 * nf) = hp1;
        *(__nv_bfloat162*)(Ol_ + base1 + 8 * nf) = lp1;
    }
}

// ---------------------------------------------------------------------------
// fp32 -> split bf16 (row-major, for input v)
// ---------------------------------------------------------------------------
__global__ __launch_bounds__(256) void split_bf16_kernel(
    const float4* __restrict__ x, __nv_bfloat162* __restrict__ hi,
    __nv_bfloat162* __restrict__ lo, int n4)
{
    int i = blockIdx.x * blockDim.x + threadIdx.x;
    if (i >= n4) return;
    float4 v = x[i];
    __nv_bfloat162 a = __floats2bfloat162_rn(v.x, v.y);
    __nv_bfloat162 b = __floats2bfloat162_rn(v.z, v.w);
    float2 fa = __bfloat1622float2(a), fb = __bfloat1622float2(b);
    __nv_bfloat162 c = __floats2bfloat162_rn(v.x - fa.x, v.y - fa.y);
    __nv_bfloat162 d = __floats2bfloat162_rn(v.z - fb.x, v.w - fb.y);
    hi[2 * i] = a; hi[2 * i + 1] = b;
    lo[2 * i] = c; lo[2 * i + 1] = d;
}

// ---------------------------------------------------------------------------
// W[K,N] fp32 -> W^T[N,K] split bf16   grid (32,32), block (32,8)
// ---------------------------------------------------------------------------
__global__ __launch_bounds__(256) void transpose_split(
    const float* __restrict__ W, __nv_bfloat16* __restrict__ Th,
    __nv_bfloat16* __restrict__ Tl)
{
    __shared__ float t[32][33];
    const int n0 = blockIdx.x * 32, k0 = blockIdx.y * 32;
    const int tx = threadIdx.x, ty = threadIdx.y;
#pragma unroll
    for (int i = 0; i < 4; i++)
        t[ty + i * 8][tx] = W[(size_t)(k0 + ty + i * 8) * D_ + n0 + tx];
    __syncthreads();
#pragma unroll
    for (int i = 0; i < 4; i++) {
        int n = n0 + ty + i * 8;
        float v = t[tx][ty + i * 8];
        __nv_bfloat16 h = __float2bfloat16(v);
        __nv_bfloat16 l = __float2bfloat16(v - __bfloat162float(h));
        Th[(size_t)n * D_ + k0 + tx] = h;
        Tl[(size_t)n * D_ + k0 + tx] = l;
    }
}

// ---------------------------------------------------------------------------
// Launch
// ---------------------------------------------------------------------------
extern "C" void kernel_launch(void* const* d_in, const int* in_sizes, int n_in,
                              void* d_out, int out_size)
{
    (void)in_sizes; (void)n_in; (void)out_size;
    const float* v       = (const float*)d_in[0];
    const int*   lengths = (const int*)  d_in[1];
    const float* Wq      = (const float*)d_in[2];
    const float* bq      = (const float*)d_in[3];
    const float* Wk      = (const float*)d_in[4];
    const float* bk      = (const float*)d_in[5];
    const float* Wv      = (const float*)d_in[6];
    const float* bv      = (const float*)d_in[7];
    const float* Wo      = (const float*)d_in[8];
    const float* bo      = (const float*)d_in[9];
    float* out = (float*)d_out;

    __nv_bfloat16 *ah, *al, *bh, *bl, *qh, *ql, *kh, *kl, *vh, *vl;
    cudaGetSymbolAddress((void**)&ah, g_Ah);
    cudaGetSymbolAddress((void**)&al, g_Al);
    cudaGetSymbolAddress((void**)&bh, g_Bh);
    cudaGetSymbolAddress((void**)&bl, g_Bl);
    cudaGetSymbolAddress((void**)&qh, g_Qh);
    cudaGetSymbolAddress((void**)&ql, g_Ql);
    cudaGetSymbolAddress((void**)&kh, g_Kh);
    cudaGetSymbolAddress((void**)&kl, g_Kl);
    cudaGetSymbolAddress((void**)&vh, g_Vh);
    cudaGetSymbolAddress((void**)&vl, g_Vl);

    cudaFuncSetAttribute(gemm_mma<0>, cudaFuncAttributeMaxDynamicSharedMemorySize, GEMM_SMEM);
    cudaFuncSetAttribute(gemm_mma<1>, cudaFuncAttributeMaxDynamicSharedMemorySize, GEMM_SMEM);
    cudaFuncSetAttribute(attn_mma, cudaFuncAttributeMaxDynamicSharedMemorySize, ATTN_SMEM);

    const int n4 = M_ * D_ / 4;
    dim3 gsplit((n4 + 255) / 256);
    dim3 gtr(32, 32), btr(32, 8);
    dim3 gg(D_ / 128, M_ / 128);   // (8, 64)

    split_bf16_kernel<<<gsplit, 256>>>((const float4*)v,
        (__nv_bfloat162*)ah, (__nv_bfloat162*)al, n4);

    transpose_split<<<gtr, btr>>>(Wq, bh, bl);
    gemm_mma<1><<<gg, 256, GEMM_SMEM>>>(ah, al, bh, bl, bq, nullptr, qh, ql);
    transpose_split<<<gtr, btr>>>(Wk, bh, bl);
    gemm_mma<1><<<gg, 256, GEMM_SMEM>>>(ah, al, bh, bl, bk, nullptr, kh, kl);
    transpose_split<<<gtr, btr>>>(Wv, bh, bl);
    gemm_mma<1><<<gg, 256, GEMM_SMEM>>>(ah, al, bh, bl, bv, nullptr, vh, vl);

    dim3 ga(S_ / 128, H_, B_);     // (4, 16, 16)
    attn_mma<<<ga, 256, ATTN_SMEM>>>(qh, ql, kh, kl, vh, vl, lengths, ah, al);

    transpose_split<<<gtr, btr>>>(Wo, bh, bl);
    gemm_mma<0><<<gg, 256, GEMM_SMEM>>>(ah, al, bh, bl, bo, out, nullptr, nullptr);
}

// round 7
// speedup vs baseline: 3.3534x; 1.1353x over previous
#include <cuda_runtime.h>
#include <cuda_bf16.h>
#include <cstdint>
#include <cstddef>

// Problem constants
#define B_  16
#define S_  512
#define D_  1024
#define H_  16
#define DH_ 64
#define M_  (B_ * S_)   // 8192

// ---------------------------------------------------------------------------
// Scratch (static device globals)
// ---------------------------------------------------------------------------
__device__ __align__(128) __nv_bfloat16 g_Ah[M_ * D_];   // v-split, later attn out (row-major)
__device__ __align__(128) __nv_bfloat16 g_Al[M_ * D_];
__device__ __align__(128) __nv_bfloat16 g_Bh[D_ * D_];   // W^T hi  [N][K]
__device__ __align__(128) __nv_bfloat16 g_Bl[D_ * D_];
__device__ __align__(128) __nv_bfloat16 g_Qh[M_ * D_];   // head-major [b,h,s,dh]
__device__ __align__(128) __nv_bfloat16 g_Ql[M_ * D_];
__device__ __align__(128) __nv_bfloat16 g_Kh[M_ * D_];
__device__ __align__(128) __nv_bfloat16 g_Kl[M_ * D_];
__device__ __align__(128) __nv_bfloat16 g_Vh[M_ * D_];
__device__ __align__(128) __nv_bfloat16 g_Vl[M_ * D_];

// ---------------------------------------------------------------------------
// PTX helpers (sm_80+ features only; compute_103 lowering rejects sm_103a-only)
// ---------------------------------------------------------------------------
__device__ __forceinline__ uint32_t smem_u32(const void* p) {
    uint32_t a;
    asm("{ .reg .u64 t; cvta.to.shared.u64 t, %1; cvt.u32.u64 %0, t; }" : "=r"(a) : "l"(p));
    return a;
}
__device__ __forceinline__ void cp16(uint32_t saddr, const void* gaddr) {
    asm volatile("cp.async.cg.shared.global [%0], [%1], 16;" :: "r"(saddr), "l"(gaddr) : "memory");
}
#define CP_COMMIT() asm volatile("cp.async.commit_group;" ::: "memory")
#define CP_WAIT0()  asm volatile("cp.async.wait_group 0;" ::: "memory")
#define CP_WAIT1()  asm volatile("cp.async.wait_group 1;" ::: "memory")
#define CP_WAIT2()  asm volatile("cp.async.wait_group 2;" ::: "memory")

__device__ __forceinline__ void ldsm4(uint32_t* r, uint32_t a) {
    asm volatile("ldmatrix.sync.aligned.m8n8.x4.shared.b16 {%0,%1,%2,%3}, [%4];"
                 : "=r"(r[0]), "=r"(r[1]), "=r"(r[2]), "=r"(r[3]) : "r"(a));
}
__device__ __forceinline__ void ldsm4t(uint32_t* r, uint32_t a) {
    asm volatile("ldmatrix.sync.aligned.m8n8.x4.trans.shared.b16 {%0,%1,%2,%3}, [%4];"
                 : "=r"(r[0]), "=r"(r[1]), "=r"(r[2]), "=r"(r[3]) : "r"(a));
}
__device__ __forceinline__ void mma16816(float* c, const uint32_t* a, const uint32_t* b) {
    asm volatile(
        "mma.sync.aligned.m16n8k16.row.col.f32.bf16.bf16.f32 "
        "{%0,%1,%2,%3}, {%4,%5,%6,%7}, {%8,%9}, {%0,%1,%2,%3};"
        : "+f"(c[0]), "+f"(c[1]), "+f"(c[2]), "+f"(c[3])
        : "r"(a[0]), "r"(a[1]), "r"(a[2]), "r"(a[3]), "r"(b[0]), "r"(b[1]));
}

#define SMEM_SWZ(o) ((o) ^ (((o) >> 3) & 0x70))

// ---------------------------------------------------------------------------
// HMMA GEMM: C = Ah@Bh^T + Ah@Bl^T + Al@Bh^T (+bias)
// MODE 0: fp32 row-major C.  MODE 1: split bf16 head-major [b,h,s,dh].
// SKIP: early-exit CTAs whose rows are never read by attention (K/V proj).
// CTA tile 128x128, BK=64, 3-stage cp.async; 8 warps 2x4, warp tile 64x32.
// ---------------------------------------------------------------------------
#define T_AH 0
#define T_AL 16384
#define T_BH 32768
#define T_BL 49152
#define STAGE_BYTES 65536
#define GEMM_SMEM (3 * STAGE_BYTES)   // 196608

__device__ __forceinline__ void load_tile16(uint32_t sdst, const __nv_bfloat16* g,
                                            int row0, int kc, int tid) {
#pragma unroll
    for (int i = 0; i < 4; i++) {
        int idx = tid + i * 256;
        int r = idx >> 3, c = idx & 7;
        const __nv_bfloat16* gp = g + (size_t)(row0 + r) * D_ + kc * 64 + c * 8;
        cp16(sdst + SMEM_SWZ(r * 128 + c * 16), gp);
    }
}

template <int MODE, bool SKIP>
__global__ __launch_bounds__(256) void gemm_mma(
    const __nv_bfloat16* __restrict__ Ah, const __nv_bfloat16* __restrict__ Al,
    const __nv_bfloat16* __restrict__ Bh, const __nv_bfloat16* __restrict__ Bl,
    const float* __restrict__ bias, float* __restrict__ C,
    __nv_bfloat16* __restrict__ Ch, __nv_bfloat16* __restrict__ Cl,
    const int* __restrict__ lengths)
{
    extern __shared__ __align__(1024) char smem[];
    const int tid  = threadIdx.x;
    const int wid  = tid >> 5, lane = tid & 31;
    const int m0   = blockIdx.y * 128;
    const int n0   = blockIdx.x * 128;

    if (SKIP) {
        // attention reads rows [0, ceil(len/64)*64) of each batch's K/V slab
        int len = lengths[m0 >> 9];
        if ((m0 & 511) >= ((len + 63) & ~63)) return;
    }

    const int wm   = (wid >> 2) * 64;
    const int wn   = (wid & 3)  * 32;
    uint32_t sb = smem_u32(smem);

    float acc[4][4][4];
#pragma unroll
    for (int i = 0; i < 4; i++)
#pragma unroll
        for (int j = 0; j < 4; j++)
#pragma unroll
            for (int k = 0; k < 4; k++) acc[i][j][k] = 0.f;

    const int a_row = wm + (lane & 15);
    const int a_coff = (lane >> 4) * 16;
    const int b_row = wn + ((lane >> 4) << 3) + (lane & 7);
    const int b_coff = ((lane >> 3) & 1) * 16;

    // prologue: chunks 0,1 -> stages 0,1
#pragma unroll
    for (int p = 0; p < 2; p++) {
        uint32_t so = sb + p * STAGE_BYTES;
        load_tile16(so + T_AH, Ah, m0, p, tid);
        load_tile16(so + T_AL, Al, m0, p, tid);
        load_tile16(so + T_BH, Bh, n0, p, tid);
        load_tile16(so + T_BL, Bl, n0, p, tid);
        CP_COMMIT();
    }

    int stage = 0, nstage = 2;
#pragma unroll 1
    for (int c = 0; c < 16; c++) {
        if (c + 2 < 16) {
            uint32_t so = sb + nstage * STAGE_BYTES;
            load_tile16(so + T_AH, Ah, m0, c + 2, tid);
            load_tile16(so + T_AL, Al, m0, c + 2, tid);
            load_tile16(so + T_BH, Bh, n0, c + 2, tid);
            load_tile16(so + T_BL, Bl, n0, c + 2, tid);
            CP_COMMIT();
            CP_WAIT2();
        } else if (c + 1 < 16) {
            CP_WAIT1();
        } else {
            CP_WAIT0();
        }
        __syncthreads();

        const uint32_t so = sb + stage * STAGE_BYTES;
#pragma unroll
        for (int ks = 0; ks < 4; ks++) {
            const int kb = ks * 32;
            uint32_t ah[4][4], al[4][4], bh[2][4], bl[2][4];
#pragma unroll
            for (int mt = 0; mt < 4; mt++) {
                uint32_t off = SMEM_SWZ((a_row + mt * 16) * 128 + kb + a_coff);
                ldsm4(ah[mt], so + T_AH + off);
                ldsm4(al[mt], so + T_AL + off);
            }
#pragma unroll
            for (int nt2 = 0; nt2 < 2; nt2++) {
                uint32_t off = SMEM_SWZ((b_row + nt2 * 16) * 128 + kb + b_coff);
                ldsm4(bh[nt2], so + T_BH + off);
                ldsm4(bl[nt2], so + T_BL + off);
            }
#pragma unroll
            for (int mt = 0; mt < 4; mt++) {
#pragma unroll
                for (int nt = 0; nt < 4; nt++) {
                    const uint32_t* fbh = &bh[nt >> 1][(nt & 1) * 2];
                    const uint32_t* fbl = &bl[nt >> 1][(nt & 1) * 2];
                    mma16816(acc[mt][nt], ah[mt], fbh);
                    mma16816(acc[mt][nt], ah[mt], fbl);
                    mma16816(acc[mt][nt], al[mt], fbh);
                }
            }
        }
        __syncthreads();
        stage = (stage + 1) == 3 ? 0 : stage + 1;
        nstage = (nstage + 1) == 3 ? 0 : nstage + 1;
    }

    const int er = lane >> 2;
    const int ec = (lane & 3) * 2;
#pragma unroll
    for (int mt = 0; mt < 4; mt++) {
#pragma unroll
        for (int nt = 0; nt < 4; nt++) {
            int row = m0 + wm + mt * 16 + er;
            int col = n0 + wn + nt * 8 + ec;
            float b0 = bias[col], b1 = bias[col + 1];
            float o0 = acc[mt][nt][0] + b0, o1 = acc[mt][nt][1] + b1;
            float o2 = acc[mt][nt][2] + b0, o3 = acc[mt][nt][3] + b1;
            if (MODE == 0) {
                float2 p0 = make_float2(o0, o1), p1 = make_float2(o2, o3);
                *(float2*)(C + (size_t)row * D_ + col) = p0;
                *(float2*)(C + (size_t)(row + 8) * D_ + col) = p1;
            } else {
                int bb = row >> 9, ss = row & 511, hh = col >> 6, dd = col & 63;
                size_t base = (((size_t)bb * H_ + hh) * S_ + ss) * DH_ + dd;
                __nv_bfloat162 hp = __floats2bfloat162_rn(o0, o1);
                float2 hf = __bfloat1622float2(hp);
                __nv_bfloat162 lp = __floats2bfloat162_rn(o0 - hf.x, o1 - hf.y);
                *(__nv_bfloat162*)(Ch + base) = hp;
                *(__nv_bfloat162*)(Cl + base) = lp;
                __nv_bfloat162 hp2 = __floats2bfloat162_rn(o2, o3);
                float2 hf2 = __bfloat1622float2(hp2);
                __nv_bfloat162 lp2 = __floats2bfloat162_rn(o2 - hf2.x, o3 - hf2.y);
                *(__nv_bfloat162*)(Ch + base + 8 * DH_) = hp2;
                *(__nv_bfloat162*)(Cl + base + 8 * DH_) = lp2;
            }
        }
    }
}

// ---------------------------------------------------------------------------
// HMMA flash attention.
// CTA = one (b,h) x 128 q rows. 8 warps x 16 rows. 64-key tiles, 2-stage.
// 3-term split everywhere: QhKh+QhKl+QlKh ; PhVh+PhVl+PlVh.
// Writes split bf16 row-major [M][D] for the O projection.
// ---------------------------------------------------------------------------
#define AQ_H 0
#define AQ_L 16384
#define AST  32768
#define AK_H 0
#define AK_L 8192
#define AV_H 16384
#define AV_L 24576
#define AST_BYTES 32768
#define ATTN_SMEM (32768 + 2 * AST_BYTES)   // 98304

__global__ __launch_bounds__(256) void attn_mma(
    const __nv_bfloat16* __restrict__ Qh_, const __nv_bfloat16* __restrict__ Ql_,
    const __nv_bfloat16* __restrict__ Kh_, const __nv_bfloat16* __restrict__ Kl_,
    const __nv_bfloat16* __restrict__ Vh_, const __nv_bfloat16* __restrict__ Vl_,
    const int* __restrict__ lengths,
    __nv_bfloat16* __restrict__ Oh_, __nv_bfloat16* __restrict__ Ol_)
{
    extern __shared__ __align__(1024) char smem[];
    const int tid = threadIdx.x, wid = tid >> 5, lane = tid & 31;
    const int b = blockIdx.z, h = blockIdx.y, q0 = blockIdx.x * 128;
    const int len = lengths[b];
    uint32_t sb = smem_u32(smem);
    const size_t bh_off = ((size_t)b * H_ + h) * (S_ * DH_);

    // Q tile load (128 rows x 128B, hi+lo)
#pragma unroll
    for (int i = 0; i < 4; i++) {
        int idx = tid + i * 256;
        int r = idx >> 3, c = idx & 7;
        cp16(sb + AQ_H + SMEM_SWZ(r * 128 + c * 16), Qh_ + bh_off + (size_t)(q0 + r) * DH_ + c * 8);
        cp16(sb + AQ_L + SMEM_SWZ(r * 128 + c * 16), Ql_ + bh_off + (size_t)(q0 + r) * DH_ + c * 8);
    }
    CP_COMMIT();

    const int jend = (len + 63) & ~63;     // <= 512
    const int ntile = jend >> 6;

    // prefetch KV tile 0 -> stage 0
    {
        uint32_t so = sb + AST;
#pragma unroll
        for (int i = 0; i < 2; i++) {
            int idx = tid + i * 256;
            int r = idx >> 3, c = idx & 7;
            size_t g = bh_off + (size_t)r * DH_ + c * 8;
            uint32_t sw = SMEM_SWZ(r * 128 + c * 16);
            cp16(so + AK_H + sw, Kh_ + g);
            cp16(so + AK_L + sw, Kl_ + g);
            cp16(so + AV_H + sw, Vh_ + g);
            cp16(so + AV_L + sw, Vl_ + g);
        }
        CP_COMMIT();
    }

    // wait for Q (KV0 may still fly), then pull Q fragments
    CP_WAIT1();
    __syncthreads();

    const int a_row = wid * 16 + (lane & 15);
    const int a_co = (lane >> 4) * 16;
    uint32_t qh[4][4], ql[4][4];
#pragma unroll
    for (int s = 0; s < 4; s++) {
        uint32_t off = SMEM_SWZ(a_row * 128 + s * 32 + a_co);
        ldsm4(qh[s], sb + AQ_H + off);
        ldsm4(ql[s], sb + AQ_L + off);
    }

    float oa[8][4];
#pragma unroll
    for (int i = 0; i < 8; i++)
#pragma unroll
        for (int j = 0; j < 4; j++) oa[i][j] = 0.f;
    float m0 = -1e30f, m1 = -1e30f, l0 = 0.f, l1 = 0.f;

    const int krow = ((lane >> 4) << 3) + (lane & 7);   // K ldsm pattern (gemm-B)
    const int kco  = ((lane >> 3) & 1) * 16;
    const int vrow = lane & 15;                          // V trans ldsm pattern
    const int vco  = (lane >> 4) * 16;

#pragma unroll 1
    for (int t = 0; t < ntile; t++) {
        CP_WAIT0();
        __syncthreads();
        if (t + 1 < ntile) {
            uint32_t so = sb + AST + ((t + 1) & 1) * AST_BYTES;
            int j0n = (t + 1) * 64;
#pragma unroll
            for (int i = 0; i < 2; i++) {
                int idx = tid + i * 256;
                int r = idx >> 3, c = idx & 7;
                size_t g = bh_off + (size_t)(j0n + r) * DH_ + c * 8;
                uint32_t sw = SMEM_SWZ(r * 128 + c * 16);
                cp16(so + AK_H + sw, Kh_ + g);
                cp16(so + AK_L + sw, Kl_ + g);
                cp16(so + AV_H + sw, Vh_ + g);
                cp16(so + AV_L + sw, Vl_ + g);
            }
            CP_COMMIT();
        }

        const uint32_t so = sb + AST + (t & 1) * AST_BYTES;
        const int j0 = t * 64;

        // ---- S = Q @ K^T (3-term split) ----
        float S[8][4];
#pragma unroll
        for (int i = 0; i < 8; i++)
#pragma unroll
            for (int j = 0; j < 4; j++) S[i][j] = 0.f;
#pragma unroll
        for (int s = 0; s < 4; s++) {
#pragma unroll
            for (int g = 0; g < 4; g++) {
                uint32_t kh4[4], kl4[4];
                uint32_t off = SMEM_SWZ((g * 16 + krow) * 128 + s * 32 + kco);
                ldsm4(kh4, so + AK_H + off);
                ldsm4(kl4, so + AK_L + off);
                mma16816(S[2 * g],     qh[s], kh4);
                mma16816(S[2 * g],     qh[s], kl4);
                mma16816(S[2 * g],     ql[s], kh4);
                mma16816(S[2 * g + 1], qh[s], kh4 + 2);
                mma16816(S[2 * g + 1], qh[s], kl4 + 2);
                mma16816(S[2 * g + 1], ql[s], kh4 + 2);
            }
        }

        // ---- scale + mask ----
        if (j0 + 64 > len) {
            int kb0 = j0 + 2 * (lane & 3);
#pragma unroll
            for (int j = 0; j < 8; j++) {
#pragma unroll
                for (int e = 0; e < 4; e++) {
                    int kk = kb0 + 8 * j + (e & 1);
                    S[j][e] = (kk < len) ? S[j][e] * 0.125f : -1e9f;
                }
            }
        } else {
#pragma unroll
            for (int j = 0; j < 8; j++)
#pragma unroll
                for (int e = 0; e < 4; e++) S[j][e] *= 0.125f;
        }

        // ---- online softmax ----
        float mx0 = -1e30f, mx1 = -1e30f;
#pragma unroll
        for (int j = 0; j < 8; j++) {
            mx0 = fmaxf(mx0, fmaxf(S[j][0], S[j][1]));
            mx1 = fmaxf(mx1, fmaxf(S[j][2], S[j][3]));
        }
        mx0 = fmaxf(mx0, __shfl_xor_sync(0xffffffffu, mx0, 1));
        mx0 = fmaxf(mx0, __shfl_xor_sync(0xffffffffu, mx0, 2));
        mx1 = fmaxf(mx1, __shfl_xor_sync(0xffffffffu, mx1, 1));
        mx1 = fmaxf(mx1, __shfl_xor_sync(0xffffffffu, mx1, 2));
        float mn0 = fmaxf(m0, mx0), mn1 = fmaxf(m1, mx1);
        float f0 = __expf(m0 - mn0), f1 = __expf(m1 - mn1);
        l0 *= f0; l1 *= f1;
#pragma unroll
        for (int i = 0; i < 8; i++) {
            oa[i][0] *= f0; oa[i][1] *= f0; oa[i][2] *= f1; oa[i][3] *= f1;
        }
        float rs0 = 0.f, rs1 = 0.f;
#pragma unroll
        for (int j = 0; j < 8; j++) {
            S[j][0] = __expf(S[j][0] - mn0);
            S[j][1] = __expf(S[j][1] - mn0);
            S[j][2] = __expf(S[j][2] - mn1);
            S[j][3] = __expf(S[j][3] - mn1);
            rs0 += S[j][0] + S[j][1];
            rs1 += S[j][2] + S[j][3];
        }
        rs0 += __shfl_xor_sync(0xffffffffu, rs0, 1);
        rs0 += __shfl_xor_sync(0xffffffffu, rs0, 2);
        rs1 += __shfl_xor_sync(0xffffffffu, rs1, 1);
        rs1 += __shfl_xor_sync(0xffffffffu, rs1, 2);
        l0 += rs0; l1 += rs1;
        m0 = mn0; m1 = mn1;

        // ---- O += P @ V (3-term split) ----
#pragma unroll
        for (int s = 0; s < 4; s++) {
            uint32_t pah[4], pal[4];
#pragma unroll
            for (int half = 0; half < 2; half++) {
                const float* Sf = S[2 * s + half];
                __nv_bfloat162 hp0 = __floats2bfloat162_rn(Sf[0], Sf[1]);
                float2 hf0 = __bfloat1622float2(hp0);
                __nv_bfloat162 lp0 = __floats2bfloat162_rn(Sf[0] - hf0.x, Sf[1] - hf0.y);
                __nv_bfloat162 hp1 = __floats2bfloat162_rn(Sf[2], Sf[3]);
                float2 hf1 = __bfloat1622float2(hp1);
                __nv_bfloat162 lp1 = __floats2bfloat162_rn(Sf[2] - hf1.x, Sf[3] - hf1.y);
                pah[2 * half]     = *(uint32_t*)&hp0;
                pah[2 * half + 1] = *(uint32_t*)&hp1;
                pal[2 * half]     = *(uint32_t*)&lp0;
                pal[2 * half + 1] = *(uint32_t*)&lp1;
            }
#pragma unroll
            for (int g = 0; g < 4; g++) {
                uint32_t vh4[4], vl4[4];
                uint32_t off = SMEM_SWZ((s * 16 + vrow) * 128 + g * 32 + vco);
                ldsm4t(vh4, so + AV_H + off);
                ldsm4t(vl4, so + AV_L + off);
                mma16816(oa[2 * g],     pah, vh4);
                mma16816(oa[2 * g],     pah, vl4);
                mma16816(oa[2 * g],     pal, vh4);
                mma16816(oa[2 * g + 1], pah, vh4 + 2);
                mma16816(oa[2 * g + 1], pah, vl4 + 2);
                mma16816(oa[2 * g + 1], pal, vh4 + 2);
            }
        }
    }

    // ---- epilogue: normalize, split, write row-major [M][D] ----
    float il0 = 1.f / l0, il1 = 1.f / l1;
    int qrow = q0 + wid * 16 + (lane >> 2);
    size_t base0 = ((size_t)b * S_ + qrow) * D_ + h * DH_ + 2 * (lane & 3);
    size_t base1 = base0 + (size_t)8 * D_;
#pragma unroll
    for (int nf = 0; nf < 8; nf++) {
        float e0 = oa[nf][0] * il0, e1 = oa[nf][1] * il0;
        float e2 = oa[nf][2] * il1, e3 = oa[nf][3] * il1;
        __nv_bfloat162 hp0 = __floats2bfloat162_rn(e0, e1);
        float2 hf0 = __bfloat1622float2(hp0);
        __nv_bfloat162 lp0 = __floats2bfloat162_rn(e0 - hf0.x, e1 - hf0.y);
        __nv_bfloat162 hp1 = __floats2bfloat162_rn(e2, e3);
        float2 hf1 = __bfloat1622float2(hp1);
        __nv_bfloat162 lp1 = __floats2bfloat162_rn(e2 - hf1.x, e3 - hf1.y);
        *(__nv_bfloat162*)(Oh_ + base0 + 8 * nf) = hp0;
        *(__nv_bfloat162*)(Ol_ + base0 + 8 * nf) = lp0;
        *(__nv_bfloat162*)(Oh_ + base1 + 8 * nf) = hp1;
        *(__nv_bfloat162*)(Ol_ + base1 + 8 * nf) = lp1;
    }
}

// ---------------------------------------------------------------------------
// fp32 -> split bf16 (row-major, for input v)
// ---------------------------------------------------------------------------
__global__ __launch_bounds__(256) void split_bf16_kernel(
    const float4* __restrict__ x, __nv_bfloat162* __restrict__ hi,
    __nv_bfloat162* __restrict__ lo, int n4)
{
    int i = blockIdx.x * blockDim.x + threadIdx.x;
    if (i >= n4) return;
    float4 v = x[i];
    __nv_bfloat162 a = __floats2bfloat162_rn(v.x, v.y);
    __nv_bfloat162 b = __floats2bfloat162_rn(v.z, v.w);
    float2 fa = __bfloat1622float2(a), fb = __bfloat1622float2(b);
    __nv_bfloat162 c = __floats2bfloat162_rn(v.x - fa.x, v.y - fa.y);
    __nv_bfloat162 d = __floats2bfloat162_rn(v.z - fb.x, v.w - fb.y);
    hi[2 * i] = a; hi[2 * i + 1] = b;
    lo[2 * i] = c; lo[2 * i + 1] = d;
}

// ---------------------------------------------------------------------------
// W[K,N] fp32 -> W^T[N,K] split bf16   grid (32,32), block (32,8)
// ---------------------------------------------------------------------------
__global__ __launch_bounds__(256) void transpose_split(
    const float* __restrict__ W, __nv_bfloat16* __restrict__ Th,
    __nv_bfloat16* __restrict__ Tl)
{
    __shared__ float t[32][33];
    const int n0 = blockIdx.x * 32, k0 = blockIdx.y * 32;
    const int tx = threadIdx.x, ty = threadIdx.y;
#pragma unroll
    for (int i = 0; i < 4; i++)
        t[ty + i * 8][tx] = W[(size_t)(k0 + ty + i * 8) * D_ + n0 + tx];
    __syncthreads();
#pragma unroll
    for (int i = 0; i < 4; i++) {
        int n = n0 + ty + i * 8;
        float v = t[tx][ty + i * 8];
        __nv_bfloat16 h = __float2bfloat16(v);
        __nv_bfloat16 l = __float2bfloat16(v - __bfloat162float(h));
        Th[(size_t)n * D_ + k0 + tx] = h;
        Tl[(size_t)n * D_ + k0 + tx] = l;
    }
}

// ---------------------------------------------------------------------------
// Launch
// ---------------------------------------------------------------------------
extern "C" void kernel_launch(void* const* d_in, const int* in_sizes, int n_in,
                              void* d_out, int out_size)
{
    (void)in_sizes; (void)n_in; (void)out_size;
    const float* v       = (const float*)d_in[0];
    const int*   lengths = (const int*)  d_in[1];
    const float* Wq      = (const float*)d_in[2];
    const float* bq      = (const float*)d_in[3];
    const float* Wk      = (const float*)d_in[4];
    const float* bk      = (const float*)d_in[5];
    const float* Wv      = (const float*)d_in[6];
    const float* bv      = (const float*)d_in[7];
    const float* Wo      = (const float*)d_in[8];
    const float* bo      = (const float*)d_in[9];
    float* out = (float*)d_out;

    __nv_bfloat16 *ah, *al, *bh, *bl, *qh, *ql, *kh, *kl, *vh, *vl;
    cudaGetSymbolAddress((void**)&ah, g_Ah);
    cudaGetSymbolAddress((void**)&al, g_Al);
    cudaGetSymbolAddress((void**)&bh, g_Bh);
    cudaGetSymbolAddress((void**)&bl, g_Bl);
    cudaGetSymbolAddress((void**)&qh, g_Qh);
    cudaGetSymbolAddress((void**)&ql, g_Ql);
    cudaGetSymbolAddress((void**)&kh, g_Kh);
    cudaGetSymbolAddress((void**)&kl, g_Kl);
    cudaGetSymbolAddress((void**)&vh, g_Vh);
    cudaGetSymbolAddress((void**)&vl, g_Vl);

    cudaFuncSetAttribute(gemm_mma<0, false>, cudaFuncAttributeMaxDynamicSharedMemorySize, GEMM_SMEM);
    cudaFuncSetAttribute(gemm_mma<1, false>, cudaFuncAttributeMaxDynamicSharedMemorySize, GEMM_SMEM);
    cudaFuncSetAttribute(gemm_mma<1, true>,  cudaFuncAttributeMaxDynamicSharedMemorySize, GEMM_SMEM);
    cudaFuncSetAttribute(attn_mma, cudaFuncAttributeMaxDynamicSharedMemorySize, ATTN_SMEM);

    const int n4 = M_ * D_ / 4;
    dim3 gsplit((n4 + 255) / 256);
    dim3 gtr(32, 32), btr(32, 8);
    dim3 gg(D_ / 128, M_ / 128);   // (8, 64)

    split_bf16_kernel<<<gsplit, 256>>>((const float4*)v,
        (__nv_bfloat162*)ah, (__nv_bfloat162*)al, n4);

    transpose_split<<<gtr, btr>>>(Wq, bh, bl);
    gemm_mma<1, false><<<gg, 256, GEMM_SMEM>>>(ah, al, bh, bl, bq, nullptr, qh, ql, nullptr);
    transpose_split<<<gtr, btr>>>(Wk, bh, bl);
    gemm_mma<1, true><<<gg, 256, GEMM_SMEM>>>(ah, al, bh, bl, bk, nullptr, kh, kl, lengths);
    transpose_split<<<gtr, btr>>>(Wv, bh, bl);
    gemm_mma<1, true><<<gg, 256, GEMM_SMEM>>>(ah, al, bh, bl, bv, nullptr, vh, vl, lengths);

    dim3 ga(S_ / 128, H_, B_);     // (4, 16, 16)
    attn_mma<<<ga, 256, ATTN_SMEM>>>(qh, ql, kh, kl, vh, vl, lengths, ah, al);

    transpose_split<<<gtr, btr>>>(Wo, bh, bl);
    gemm_mma<0, false><<<gg, 256, GEMM_SMEM>>>(ah, al, bh, bl, bo, out, nullptr, nullptr, nullptr);
}